// round 3
// baseline (speedup 1.0000x reference)
#include <cuda_runtime.h>
#include <math.h>

#define D_IN 768
#define NQ_MAX 512
#define NC_MAX 65536
#define EPSF 1e-7f

// Scratch: corpus features transposed [feature k][corpus idx], plus per-row extras.
__device__ float g_cT[64 * NC_MAX];     // k-major corpus features (e:0..31, h:32..47, s:48..63)
__device__ float g_yn[NC_MAX];          // ||c_h||^2 = tanh(n)^2
__device__ float g_qT[64 * NQ_MAX];     // k-major query features
__device__ float g_xn[NQ_MAX];          // ||q_h||^2
__device__ float g_w[3 * NQ_MAX];       // softplus weights per query

// ---------------------------------------------------------------------------
// Kernel A: corpus projection. Block = 64 corpus rows, 256 threads.
// thread (k = tid&63, rg = tid>>6) computes feature k for rows rg*16 .. rg*16+15.
// ---------------------------------------------------------------------------
__global__ __launch_bounds__(256) void corpus_proj_kernel(
    const float* __restrict__ xc,
    const float* __restrict__ We, const float* __restrict__ be,
    const float* __restrict__ Wh, const float* __restrict__ bh,
    const float* __restrict__ Ws, const float* __restrict__ bs,
    const float* __restrict__ scale_h_p, int NC)
{
    __shared__ float xs[64 * 68];   // xs[row][kk], stride 68 (float4-aligned, conflict-free)
    __shared__ float wt[64 * 65];   // wt[kk][k], stride 65; reused as transpose buffer
    __shared__ float sm_yn[64];

    const int tid = threadIdx.x;
    const int k   = tid & 63;
    const int rg  = tid >> 6;          // 0..3
    const int c0  = blockIdx.x * 64;

    float bias;
    if (k < 32)       bias = be[k];
    else if (k < 48)  bias = bh[k - 32];
    else              bias = bs[k - 48];

    float acc[16];
#pragma unroll
    for (int i = 0; i < 16; i++) acc[i] = 0.f;

    for (int k0 = 0; k0 < D_IN; k0 += 64) {
        __syncthreads();
        // load x tile: 64 rows x 64 k, coalesced
#pragma unroll
        for (int it = 0; it < 16; it++) {
            int idx = tid + it * 256;
            int r = idx >> 6, j = idx & 63;
            xs[r * 68 + j] = xc[(size_t)(c0 + r) * D_IN + k0 + j];
        }
        // load weight tile transposed: wt[j][kf] = W_kf[k0+j], coalesced along j
#pragma unroll
        for (int it = 0; it < 16; it++) {
            int idx = tid + it * 256;
            int kf = idx >> 6, j = idx & 63;
            const float* wr = (kf < 32) ? (We + kf * D_IN)
                            : (kf < 48) ? (Wh + (kf - 32) * D_IN)
                                        : (Ws + (kf - 48) * D_IN);
            wt[j * 65 + kf] = wr[k0 + j];
        }
        __syncthreads();
#pragma unroll
        for (int kk = 0; kk < 64; kk += 4) {
            float w0 = wt[(kk + 0) * 65 + k];
            float w1 = wt[(kk + 1) * 65 + k];
            float w2 = wt[(kk + 2) * 65 + k];
            float w3 = wt[(kk + 3) * 65 + k];
#pragma unroll
            for (int i = 0; i < 16; i++) {
                const float4 xv = *(const float4*)&xs[(rg * 16 + i) * 68 + kk]; // broadcast
                acc[i] = fmaf(xv.x, w0, acc[i]);
                acc[i] = fmaf(xv.y, w1, acc[i]);
                acc[i] = fmaf(xv.z, w2, acc[i]);
                acc[i] = fmaf(xv.w, w3, acc[i]);
            }
        }
    }

    // bias (+ scale_h for hyperbolic branch)
    const float sh = scale_h_p[0];
    const bool isE = (k < 32);
    const bool isH = (k >= 32) && (k < 48);
#pragma unroll
    for (int i = 0; i < 16; i++) {
        float v = acc[i] + bias;
        if (isH) v *= sh;
        acc[i] = v;
    }

    // per-row norms via warp shuffles.
    // even warps: k in [0,32) -> e-norm over full warp.
    // odd warps: lanes 0..15 = h (k 32..47), lanes 16..31 = s (k 48..63), 16-lane groups.
    const unsigned FULL = 0xffffffffu;
    if (isE) {
#pragma unroll
        for (int i = 0; i < 16; i++) {
            float s = acc[i] * acc[i];
            s += __shfl_xor_sync(FULL, s, 16);
            s += __shfl_xor_sync(FULL, s, 8);
            s += __shfl_xor_sync(FULL, s, 4);
            s += __shfl_xor_sync(FULL, s, 2);
            s += __shfl_xor_sync(FULL, s, 1);
            acc[i] = acc[i] / sqrtf(s);
        }
    } else {
#pragma unroll
        for (int i = 0; i < 16; i++) {
            float s = acc[i] * acc[i];
            s += __shfl_xor_sync(FULL, s, 8);
            s += __shfl_xor_sync(FULL, s, 4);
            s += __shfl_xor_sync(FULL, s, 2);
            s += __shfl_xor_sync(FULL, s, 1);
            if (isH) {
                float n  = fmaxf(sqrtf(s), 1e-15f);
                float tn = tanhf(n);
                acc[i] = acc[i] * (tn / n);
                if (k == 32) sm_yn[rg * 16 + i] = tn * tn;
            } else {
                acc[i] = acc[i] / sqrtf(s);
            }
        }
    }

    // transpose through smem (reuse wt) for coalesced k-major global writes
    __syncthreads();
    float* st = wt;
#pragma unroll
    for (int i = 0; i < 16; i++) st[k * 65 + rg * 16 + i] = acc[i];
    __syncthreads();
#pragma unroll
    for (int it = 0; it < 16; it++) {
        int idx = tid + it * 256;
        int kf = idx >> 6, r = idx & 63;
        g_cT[(size_t)kf * NC + c0 + r] = st[kf * 65 + r];
    }
    if (tid < 64) g_yn[c0 + tid] = sm_yn[tid];
}

// ---------------------------------------------------------------------------
// Kernel B: query projection + softplus-MLP weights. One block per query.
// ---------------------------------------------------------------------------
__global__ __launch_bounds__(128) void query_proj_kernel(
    const float* __restrict__ xq,
    const float* __restrict__ We, const float* __restrict__ be,
    const float* __restrict__ Wh, const float* __restrict__ bh,
    const float* __restrict__ Ws, const float* __restrict__ bs,
    const float* __restrict__ scale_h_p,
    const float* __restrict__ W1, const float* __restrict__ b1,
    const float* __restrict__ W2, const float* __restrict__ b2,
    int NQ)
{
    __shared__ float x[D_IN];
    __shared__ float raw[96];
    const int tid = threadIdx.x;
    const int qi  = blockIdx.x;

    for (int j = tid; j < D_IN; j += 128) x[j] = xq[(size_t)qi * D_IN + j];
    __syncthreads();

    if (tid < 96) {
        const float* Wr; float b;
        if (tid < 32)      { Wr = We + tid * D_IN;        b = be[tid]; }
        else if (tid < 48) { Wr = Wh + (tid - 32) * D_IN; b = bh[tid - 32]; }
        else if (tid < 64) { Wr = Ws + (tid - 48) * D_IN; b = bs[tid - 48]; }
        else               { Wr = W1 + (tid - 64) * D_IN; b = b1[tid - 64]; }
        float a0 = 0.f, a1 = 0.f, a2 = 0.f, a3 = 0.f;
#pragma unroll 4
        for (int j = 0; j < D_IN; j += 4) {
            const float4 wv = *(const float4*)&Wr[j];
            a0 = fmaf(x[j + 0], wv.x, a0);
            a1 = fmaf(x[j + 1], wv.y, a1);
            a2 = fmaf(x[j + 2], wv.z, a2);
            a3 = fmaf(x[j + 3], wv.w, a3);
        }
        float acc = (a0 + a1) + (a2 + a3) + b;
        if (tid >= 32 && tid < 48) acc *= scale_h_p[0];
        raw[tid] = acc;
    }
    __syncthreads();

    const unsigned FULL = 0xffffffffu;
    const int warp = tid >> 5, lane = tid & 31;
    if (warp == 0) {
        // e: normalize over 32
        float v = raw[lane];
        float s = v * v;
        s += __shfl_xor_sync(FULL, s, 16);
        s += __shfl_xor_sync(FULL, s, 8);
        s += __shfl_xor_sync(FULL, s, 4);
        s += __shfl_xor_sync(FULL, s, 2);
        s += __shfl_xor_sync(FULL, s, 1);
        g_qT[(size_t)lane * NQ + qi] = v / sqrtf(s);
    } else if (warp == 1) {
        // lanes 0..15: h (expmap0), lanes 16..31: s (normalize)
        float v = (lane < 16) ? raw[32 + lane] : raw[48 + (lane - 16)];
        float s = v * v;
        s += __shfl_xor_sync(FULL, s, 8);
        s += __shfl_xor_sync(FULL, s, 4);
        s += __shfl_xor_sync(FULL, s, 2);
        s += __shfl_xor_sync(FULL, s, 1);
        if (lane < 16) {
            float n  = fmaxf(sqrtf(s), 1e-15f);
            float tn = tanhf(n);
            g_qT[(size_t)(32 + lane) * NQ + qi] = v * (tn / n);
            if (lane == 0) g_xn[qi] = tn * tn;
        } else {
            g_qT[(size_t)(48 + (lane - 16)) * NQ + qi] = v / sqrtf(s);
        }
    } else if (warp == 2) {
        // weights MLP: relu(hidden) @ W2^T + b2 -> softplus
        float h = fmaxf(raw[64 + lane], 0.f);
#pragma unroll
        for (int j = 0; j < 3; j++) {
            float p = h * W2[j * 32 + lane];
            p += __shfl_xor_sync(FULL, p, 16);
            p += __shfl_xor_sync(FULL, p, 8);
            p += __shfl_xor_sync(FULL, p, 4);
            p += __shfl_xor_sync(FULL, p, 2);
            p += __shfl_xor_sync(FULL, p, 1);
            if (lane == 0) {
                p += b2[j];
                float sp = (p > 0.f) ? (p + log1pf(expf(-p))) : log1pf(expf(p));
                g_w[j * NQ + qi] = sp;
            }
        }
    }
}

// ---------------------------------------------------------------------------
// Kernel C: pairwise distances. 64q x 64c tile per block, 4x4 per thread.
// ---------------------------------------------------------------------------
__device__ __forceinline__ void mma16(float* A, float4 q, float4 c) {
    A[ 0] = fmaf(q.x, c.x, A[ 0]); A[ 1] = fmaf(q.x, c.y, A[ 1]);
    A[ 2] = fmaf(q.x, c.z, A[ 2]); A[ 3] = fmaf(q.x, c.w, A[ 3]);
    A[ 4] = fmaf(q.y, c.x, A[ 4]); A[ 5] = fmaf(q.y, c.y, A[ 5]);
    A[ 6] = fmaf(q.y, c.z, A[ 6]); A[ 7] = fmaf(q.y, c.w, A[ 7]);
    A[ 8] = fmaf(q.z, c.x, A[ 8]); A[ 9] = fmaf(q.z, c.y, A[ 9]);
    A[10] = fmaf(q.z, c.z, A[10]); A[11] = fmaf(q.z, c.w, A[11]);
    A[12] = fmaf(q.w, c.x, A[12]); A[13] = fmaf(q.w, c.y, A[13]);
    A[14] = fmaf(q.w, c.z, A[14]); A[15] = fmaf(q.w, c.w, A[15]);
}

__global__ __launch_bounds__(256) void pairwise_kernel(
    float* __restrict__ out, int NQ, int NC)
{
    __shared__ float qs[64 * 64];   // qs[k][q_local]
    __shared__ float cs[64 * 64];   // cs[k][c_local]
    __shared__ float xns[64], yns[64], w0s[64], w1s[64], w2s[64];

    const int tid = threadIdx.x;
    const int q0 = blockIdx.y * 64;
    const int c0 = blockIdx.x * 64;

#pragma unroll
    for (int it = 0; it < 16; it++) {
        int idx = tid + it * 256;
        int kf = idx >> 6, r = idx & 63;
        qs[idx] = g_qT[(size_t)kf * NQ + q0 + r];
        cs[idx] = g_cT[(size_t)kf * NC + c0 + r];
    }
    if (tid < 64) {
        xns[tid] = g_xn[q0 + tid];
        yns[tid] = g_yn[c0 + tid];
        w0s[tid] = g_w[0 * NQ + q0 + tid];
        w1s[tid] = g_w[1 * NQ + q0 + tid];
        w2s[tid] = g_w[2 * NQ + q0 + tid];
    }
    __syncthreads();

    const int tx = tid & 15, ty = tid >> 4;
    float aE[16], aH[16], aS[16];
#pragma unroll
    for (int i = 0; i < 16; i++) { aE[i] = 0.f; aH[i] = 0.f; aS[i] = 0.f; }

    const float* qb = qs + ty * 4;
    const float* cb = cs + tx * 4;
#pragma unroll
    for (int k = 0; k < 32; k++) {
        float4 qv = *(const float4*)&qb[k * 64];
        float4 cv = *(const float4*)&cb[k * 64];
        mma16(aE, qv, cv);
    }
#pragma unroll
    for (int k = 32; k < 48; k++) {
        float4 qv = *(const float4*)&qb[k * 64];
        float4 cv = *(const float4*)&cb[k * 64];
        mma16(aH, qv, cv);
    }
#pragma unroll
    for (int k = 48; k < 64; k++) {
        float4 qv = *(const float4*)&qb[k * 64];
        float4 cv = *(const float4*)&cb[k * 64];
        mma16(aS, qv, cv);
    }

#pragma unroll
    for (int i = 0; i < 4; i++) {
        const int ql  = ty * 4 + i;
        const float xn   = xns[ql];
        const float beta = 1.f - xn;
        const float w0 = w0s[ql], w1 = w1s[ql], w2 = w2s[ql];
        float r4[4];
#pragma unroll
        for (int j = 0; j < 4; j++) {
            const int cl = tx * 4 + j;
            // euclidean on unit sphere
            float de = 2.f - 2.f * aE[i * 4 + j];
            // spherical
            float dsd = fminf(fmaxf(aS[i * 4 + j], -1.f + EPSF), 1.f - EPSF);
            float ac  = acosf(dsd);
            float dss = ac * ac;
            // hyperbolic (Poincare, c=1)
            float dot = aH[i * 4 + j];
            float yn  = yns[cl];
            float alpha  = 1.f - 2.f * dot + yn;
            float num_sq = alpha * alpha * xn - 2.f * alpha * beta * dot + beta * beta * yn;
            float den    = fmaxf(1.f - 2.f * dot + xn * yn, 1e-15f);
            float t = sqrtf(fmaxf(num_sq, 0.f)) / den;
            t = fminf(fmaxf(t, 0.f), 1.f - EPSF);
            float dh  = 2.f * atanhf(t);
            float dhs = dh * dh;
            r4[j] = -(w0 * de + w1 * dhs + w2 * dss);
        }
        *(float4*)&out[(size_t)(q0 + ql) * NC + c0 + tx * 4] =
            make_float4(r4[0], r4[1], r4[2], r4[3]);
    }
}

// ---------------------------------------------------------------------------
extern "C" void kernel_launch(void* const* d_in, const int* in_sizes, int n_in,
                              void* d_out, int out_size)
{
    const float* xq      = (const float*)d_in[0];
    const float* xc      = (const float*)d_in[1];
    const float* We      = (const float*)d_in[2];
    const float* be      = (const float*)d_in[3];
    const float* Wh      = (const float*)d_in[4];
    const float* bh      = (const float*)d_in[5];
    const float* Ws      = (const float*)d_in[6];
    const float* bs      = (const float*)d_in[7];
    const float* scale_h = (const float*)d_in[8];
    const float* W1      = (const float*)d_in[9];
    const float* b1      = (const float*)d_in[10];
    const float* W2      = (const float*)d_in[11];
    const float* b2      = (const float*)d_in[12];

    const int NQ = in_sizes[0] / D_IN;   // 512
    const int NC = in_sizes[1] / D_IN;   // 65536

    corpus_proj_kernel<<<NC / 64, 256>>>(xc, We, be, Wh, bh, Ws, bs, scale_h, NC);
    query_proj_kernel<<<NQ, 128>>>(xq, We, be, Wh, bh, Ws, bs, scale_h, W1, b1, W2, b2, NQ);
    pairwise_kernel<<<dim3(NC / 64, NQ / 64), 256>>>((float*)d_out, NQ, NC);
}

// round 4
// speedup vs baseline: 1.2686x; 1.2686x over previous
#include <cuda_runtime.h>
#include <math.h>

#define D_IN 768
#define NQ_MAX 512
#define NC_MAX 65536
#define EPSF 1e-7f

typedef unsigned long long ull;

// Scratch: corpus features transposed [feature k][corpus idx], plus per-row extras.
__device__ float g_cT[64 * NC_MAX];     // k-major corpus features (e:0..31, h:32..47, s:48..63)
__device__ float g_yn[NC_MAX];          // ||c_h||^2 = tanh(n)^2
__device__ float g_qT[64 * NQ_MAX];     // k-major query features
__device__ float g_xn[NQ_MAX];          // ||q_h||^2
__device__ float g_w[3 * NQ_MAX];       // softplus weights per query

// packed f32x2 FMA: d = a*b + d (lanewise on 2 packed floats)
__device__ __forceinline__ void ffma2(ull& d, ull a, ull b) {
    asm("fma.rn.f32x2 %0, %1, %2, %0;" : "+l"(d) : "l"(a), "l"(b));
}
__device__ __forceinline__ float fold2(ull v) {
    return __uint_as_float((unsigned)v) + __uint_as_float((unsigned)(v >> 32));
}

// ---------------------------------------------------------------------------
// Kernel A: corpus projection. Block = 64 corpus rows, 256 threads.
// thread (k = tid&63, rg = tid>>6) computes feature k for rows rg*16 .. rg*16+15.
// Packed-k f32x2 mainloop. Tiles stored row-major, stride 34 float2 (pad).
// ---------------------------------------------------------------------------
#define XSTRIDE 34   // float2 units per row (32 kk + 2 pad), even -> 16B aligned

__global__ __launch_bounds__(256, 2) void corpus_proj_kernel(
    const float* __restrict__ xc,
    const float* __restrict__ We, const float* __restrict__ be,
    const float* __restrict__ Wh, const float* __restrict__ bh,
    const float* __restrict__ Ws, const float* __restrict__ bs,
    const float* __restrict__ scale_h_p, int NC)
{
    // pool: xs2 (64*34 float2) + wt2 (64*34 float2); st transpose overlays xs2
    __shared__ __align__(16) float pool[2 * 64 * XSTRIDE * 2];
    __shared__ float sm_yn[64];
    float2* xs2 = (float2*)pool;                    // [row][kk]
    float2* wt2 = (float2*)pool + 64 * XSTRIDE;     // [kf ][kk]

    const int tid = threadIdx.x;
    const int k   = tid & 63;
    const int rg  = tid >> 6;          // 0..3
    const int c0  = blockIdx.x * 64;

    float bias;
    if (k < 32)       bias = be[k];
    else if (k < 48)  bias = bh[k - 32];
    else              bias = bs[k - 48];

    ull acc2[16];
#pragma unroll
    for (int i = 0; i < 16; i++) acc2[i] = 0ull;

    const int j4 = tid & 15;           // float4 column within tile
    const int r0 = tid >> 4;           // base row / feature for loads

    for (int k0 = 0; k0 < D_IN; k0 += 64) {
        __syncthreads();
        // x tile: 64 rows x 64 k as float4 LDG, STS.128 into [row][kk] pairs
#pragma unroll
        for (int it = 0; it < 4; it++) {
            int r = r0 + it * 16;
            float4 v = *(const float4*)&xc[(size_t)(c0 + r) * D_IN + k0 + j4 * 4];
            *(float4*)&xs2[r * XSTRIDE + j4 * 2] = v;
        }
        // weight tile: wt2[kf][kk] pairs along input dim
#pragma unroll
        for (int it = 0; it < 4; it++) {
            int kf = r0 + it * 16;
            const float* wr = (kf < 32) ? (We + kf * D_IN)
                            : (kf < 48) ? (Wh + (kf - 32) * D_IN)
                                        : (Ws + (kf - 48) * D_IN);
            float4 v = *(const float4*)&wr[k0 + j4 * 4];
            *(float4*)&wt2[kf * XSTRIDE + j4 * 2] = v;
        }
        __syncthreads();

        const float2* xrow = xs2 + rg * 16 * XSTRIDE;
#pragma unroll 8
        for (int kk = 0; kk < 32; kk += 2) {
            ulonglong2 wv = *(const ulonglong2*)&wt2[k * XSTRIDE + kk];  // (w[2kk],w[2kk+1]),(w[2kk+2],w[2kk+3])
#pragma unroll
            for (int u = 0; u < 16; u++) {
                ulonglong2 xv = *(const ulonglong2*)&xrow[u * XSTRIDE + kk];  // broadcast
                ffma2(acc2[u], xv.x, wv.x);
                ffma2(acc2[u], xv.y, wv.y);
            }
        }
    }

    // fold packed halves, add bias (+ scale_h for hyperbolic branch)
    const float sh = scale_h_p[0];
    const bool isE = (k < 32);
    const bool isH = (k >= 32) && (k < 48);
    float acc[16];
#pragma unroll
    for (int i = 0; i < 16; i++) {
        float v = fold2(acc2[i]) + bias;
        if (isH) v *= sh;
        acc[i] = v;
    }

    // per-row norms via warp shuffles.
    const unsigned FULL = 0xffffffffu;
    if (isE) {
#pragma unroll
        for (int i = 0; i < 16; i++) {
            float s = acc[i] * acc[i];
            s += __shfl_xor_sync(FULL, s, 16);
            s += __shfl_xor_sync(FULL, s, 8);
            s += __shfl_xor_sync(FULL, s, 4);
            s += __shfl_xor_sync(FULL, s, 2);
            s += __shfl_xor_sync(FULL, s, 1);
            acc[i] = acc[i] / sqrtf(s);
        }
    } else {
#pragma unroll
        for (int i = 0; i < 16; i++) {
            float s = acc[i] * acc[i];
            s += __shfl_xor_sync(FULL, s, 8);
            s += __shfl_xor_sync(FULL, s, 4);
            s += __shfl_xor_sync(FULL, s, 2);
            s += __shfl_xor_sync(FULL, s, 1);
            if (isH) {
                float n  = fmaxf(sqrtf(s), 1e-15f);
                float tn = tanhf(n);
                acc[i] = acc[i] * (tn / n);
                if (k == 32) sm_yn[rg * 16 + i] = tn * tn;
            } else {
                acc[i] = acc[i] / sqrtf(s);
            }
        }
    }

    // transpose through smem (overlay pool) for coalesced k-major global writes
    __syncthreads();
    float* st = pool;   // needs 64*65 = 4160 floats; pool has 8704
#pragma unroll
    for (int i = 0; i < 16; i++) st[k * 65 + rg * 16 + i] = acc[i];
    __syncthreads();
#pragma unroll
    for (int it = 0; it < 16; it++) {
        int idx = tid + it * 256;
        int kf = idx >> 6, r = idx & 63;
        g_cT[(size_t)kf * NC + c0 + r] = st[kf * 65 + r];
    }
    if (tid < 64) g_yn[c0 + tid] = sm_yn[tid];
}

// ---------------------------------------------------------------------------
// Kernel B: query projection + softplus-MLP weights. One block per query.
// ---------------------------------------------------------------------------
__global__ __launch_bounds__(128) void query_proj_kernel(
    const float* __restrict__ xq,
    const float* __restrict__ We, const float* __restrict__ be,
    const float* __restrict__ Wh, const float* __restrict__ bh,
    const float* __restrict__ Ws, const float* __restrict__ bs,
    const float* __restrict__ scale_h_p,
    const float* __restrict__ W1, const float* __restrict__ b1,
    const float* __restrict__ W2, const float* __restrict__ b2,
    int NQ)
{
    __shared__ float x[D_IN];
    __shared__ float raw[96];
    const int tid = threadIdx.x;
    const int qi  = blockIdx.x;

    for (int j = tid; j < D_IN; j += 128) x[j] = xq[(size_t)qi * D_IN + j];
    __syncthreads();

    if (tid < 96) {
        const float* Wr; float b;
        if (tid < 32)      { Wr = We + tid * D_IN;        b = be[tid]; }
        else if (tid < 48) { Wr = Wh + (tid - 32) * D_IN; b = bh[tid - 32]; }
        else if (tid < 64) { Wr = Ws + (tid - 48) * D_IN; b = bs[tid - 48]; }
        else               { Wr = W1 + (tid - 64) * D_IN; b = b1[tid - 64]; }
        float a0 = 0.f, a1 = 0.f, a2 = 0.f, a3 = 0.f;
#pragma unroll 4
        for (int j = 0; j < D_IN; j += 4) {
            const float4 wv = *(const float4*)&Wr[j];
            a0 = fmaf(x[j + 0], wv.x, a0);
            a1 = fmaf(x[j + 1], wv.y, a1);
            a2 = fmaf(x[j + 2], wv.z, a2);
            a3 = fmaf(x[j + 3], wv.w, a3);
        }
        float acc = (a0 + a1) + (a2 + a3) + b;
        if (tid >= 32 && tid < 48) acc *= scale_h_p[0];
        raw[tid] = acc;
    }
    __syncthreads();

    const unsigned FULL = 0xffffffffu;
    const int warp = tid >> 5, lane = tid & 31;
    if (warp == 0) {
        float v = raw[lane];
        float s = v * v;
        s += __shfl_xor_sync(FULL, s, 16);
        s += __shfl_xor_sync(FULL, s, 8);
        s += __shfl_xor_sync(FULL, s, 4);
        s += __shfl_xor_sync(FULL, s, 2);
        s += __shfl_xor_sync(FULL, s, 1);
        g_qT[(size_t)lane * NQ + qi] = v / sqrtf(s);
    } else if (warp == 1) {
        float v = (lane < 16) ? raw[32 + lane] : raw[48 + (lane - 16)];
        float s = v * v;
        s += __shfl_xor_sync(FULL, s, 8);
        s += __shfl_xor_sync(FULL, s, 4);
        s += __shfl_xor_sync(FULL, s, 2);
        s += __shfl_xor_sync(FULL, s, 1);
        if (lane < 16) {
            float n  = fmaxf(sqrtf(s), 1e-15f);
            float tn = tanhf(n);
            g_qT[(size_t)(32 + lane) * NQ + qi] = v * (tn / n);
            if (lane == 0) g_xn[qi] = tn * tn;
        } else {
            g_qT[(size_t)(48 + (lane - 16)) * NQ + qi] = v / sqrtf(s);
        }
    } else if (warp == 2) {
        float h = fmaxf(raw[64 + lane], 0.f);
#pragma unroll
        for (int j = 0; j < 3; j++) {
            float p = h * W2[j * 32 + lane];
            p += __shfl_xor_sync(FULL, p, 16);
            p += __shfl_xor_sync(FULL, p, 8);
            p += __shfl_xor_sync(FULL, p, 4);
            p += __shfl_xor_sync(FULL, p, 2);
            p += __shfl_xor_sync(FULL, p, 1);
            if (lane == 0) {
                p += b2[j];
                float sp = (p > 0.f) ? (p + log1pf(expf(-p))) : log1pf(expf(p));
                g_w[j * NQ + qi] = sp;
            }
        }
    }
}

// ---------------------------------------------------------------------------
// Kernel C: pairwise distances. 64q x 64c tile per block, 4x4 per thread.
// Packed-k f32x2 mainloop; per-segment accumulator fold keeps regs bounded.
// smem layout: [kk][r] of float2 = (feat[2kk][r], feat[2kk+1][r]).
// ---------------------------------------------------------------------------
__global__ __launch_bounds__(256) void pairwise_kernel(
    float* __restrict__ out, int NQ, int NC)
{
    __shared__ __align__(16) float qs2[32 * 64 * 2];
    __shared__ __align__(16) float cs2[32 * 64 * 2];
    __shared__ float xns[64], yns[64], w0s[64], w1s[64], w2s[64];

    const int tid = threadIdx.x;
    const int q0 = blockIdx.y * 64;
    const int c0 = blockIdx.x * 64;

#pragma unroll
    for (int it = 0; it < 16; it++) {
        int idx = tid + it * 256;       // 0..4095
        int kf = idx >> 6, r = idx & 63;
        int saddr = ((kf >> 1) * 64 + r) * 2 + (kf & 1);
        qs2[saddr] = g_qT[(size_t)kf * NQ + q0 + r];
        cs2[saddr] = g_cT[(size_t)kf * NC + c0 + r];
    }
    if (tid < 64) {
        xns[tid] = g_xn[q0 + tid];
        yns[tid] = g_yn[c0 + tid];
        w0s[tid] = g_w[0 * NQ + q0 + tid];
        w1s[tid] = g_w[1 * NQ + q0 + tid];
        w2s[tid] = g_w[2 * NQ + q0 + tid];
    }
    __syncthreads();

    const int tx = tid & 15, ty = tid >> 4;
    const ulonglong2* qp = (const ulonglong2*)qs2;   // 32 per kk row
    const ulonglong2* cp = (const ulonglong2*)cs2;

    ull acc2[16];
    float aE[16], aH[16];

#define MMA_STEP(kk)                                                        \
    {                                                                       \
        ulonglong2 qA = qp[(kk) * 32 + ty * 2];                             \
        ulonglong2 qB = qp[(kk) * 32 + ty * 2 + 1];                         \
        ulonglong2 cA = cp[(kk) * 32 + tx * 2];                             \
        ulonglong2 cB = cp[(kk) * 32 + tx * 2 + 1];                         \
        ffma2(acc2[ 0], qA.x, cA.x); ffma2(acc2[ 1], qA.x, cA.y);           \
        ffma2(acc2[ 2], qA.x, cB.x); ffma2(acc2[ 3], qA.x, cB.y);           \
        ffma2(acc2[ 4], qA.y, cA.x); ffma2(acc2[ 5], qA.y, cA.y);           \
        ffma2(acc2[ 6], qA.y, cB.x); ffma2(acc2[ 7], qA.y, cB.y);           \
        ffma2(acc2[ 8], qB.x, cA.x); ffma2(acc2[ 9], qB.x, cA.y);           \
        ffma2(acc2[10], qB.x, cB.x); ffma2(acc2[11], qB.x, cB.y);           \
        ffma2(acc2[12], qB.y, cA.x); ffma2(acc2[13], qB.y, cA.y);           \
        ffma2(acc2[14], qB.y, cB.x); ffma2(acc2[15], qB.y, cB.y);           \
    }

    // E segment: kk 0..15 (k 0..31)
#pragma unroll
    for (int i = 0; i < 16; i++) acc2[i] = 0ull;
#pragma unroll
    for (int kk = 0; kk < 16; kk++) MMA_STEP(kk);
#pragma unroll
    for (int i = 0; i < 16; i++) { aE[i] = fold2(acc2[i]); acc2[i] = 0ull; }

    // H segment: kk 16..23 (k 32..47)
#pragma unroll
    for (int kk = 16; kk < 24; kk++) MMA_STEP(kk);
#pragma unroll
    for (int i = 0; i < 16; i++) { aH[i] = fold2(acc2[i]); acc2[i] = 0ull; }

    // S segment: kk 24..31 (k 48..63)
#pragma unroll
    for (int kk = 24; kk < 32; kk++) MMA_STEP(kk);

#pragma unroll
    for (int i = 0; i < 4; i++) {
        const int ql   = ty * 4 + i;
        const float xn   = xns[ql];
        const float beta = 1.f - xn;
        const float w0 = w0s[ql], w1 = w1s[ql], w2 = w2s[ql];
        float r4[4];
#pragma unroll
        for (int j = 0; j < 4; j++) {
            const int cl = tx * 4 + j;
            // euclidean on unit sphere
            float de = 2.f - 2.f * aE[i * 4 + j];
            // spherical
            float dsd = fminf(fmaxf(fold2(acc2[i * 4 + j]), -1.f + EPSF), 1.f - EPSF);
            float ac  = acosf(dsd);
            float dss = ac * ac;
            // hyperbolic (Poincare, c=1): dh = 2*atanh(t) = log((den+sn)/(den-sn))
            float dot = aH[i * 4 + j];
            float yn  = yns[cl];
            float alpha  = 1.f - 2.f * dot + yn;
            float num_sq = alpha * alpha * xn - 2.f * alpha * beta * dot + beta * beta * yn;
            float den    = fmaxf(1.f - 2.f * dot + xn * yn, 1e-15f);
            float sn = sqrtf(fmaxf(num_sq, 0.f));
            sn = fminf(sn, den * (1.f - EPSF));       // t <= 1 - EPS
            float dh  = __logf(__fdividef(den + sn, den - sn));
            float dhs = dh * dh;
            r4[j] = -(w0 * de + w1 * dhs + w2 * dss);
        }
        *(float4*)&out[(size_t)(q0 + ql) * NC + c0 + tx * 4] =
            make_float4(r4[0], r4[1], r4[2], r4[3]);
    }
#undef MMA_STEP
}

// ---------------------------------------------------------------------------
extern "C" void kernel_launch(void* const* d_in, const int* in_sizes, int n_in,
                              void* d_out, int out_size)
{
    const float* xq      = (const float*)d_in[0];
    const float* xc      = (const float*)d_in[1];
    const float* We      = (const float*)d_in[2];
    const float* be      = (const float*)d_in[3];
    const float* Wh      = (const float*)d_in[4];
    const float* bh      = (const float*)d_in[5];
    const float* Ws      = (const float*)d_in[6];
    const float* bs      = (const float*)d_in[7];
    const float* scale_h = (const float*)d_in[8];
    const float* W1      = (const float*)d_in[9];
    const float* b1      = (const float*)d_in[10];
    const float* W2      = (const float*)d_in[11];
    const float* b2      = (const float*)d_in[12];

    const int NQ = in_sizes[0] / D_IN;   // 512
    const int NC = in_sizes[1] / D_IN;   // 65536

    corpus_proj_kernel<<<NC / 64, 256>>>(xc, We, be, Wh, bh, Ws, bs, scale_h, NC);
    query_proj_kernel<<<NQ, 128>>>(xq, We, be, Wh, bh, Ws, bs, scale_h, W1, b1, W2, b2, NQ);
    pairwise_kernel<<<dim3(NC / 64, NQ / 64), 256>>>((float*)d_out, NQ, NC);
}

// round 7
// speedup vs baseline: 1.4855x; 1.1710x over previous
#include <cuda_runtime.h>
#include <math.h>

#define D_IN 768
#define NQ_MAX 512
#define NC_MAX 65536
#define EPSF 1e-7f

typedef unsigned long long ull;

// Scratch: corpus features transposed [feature k][corpus idx], plus per-row extras.
__device__ float g_cT[64 * NC_MAX];     // k-major corpus features (e:0..31, h:32..47, s:48..63)
__device__ float g_yn[NC_MAX];          // ||c_h||^2 = tanh(n)^2
__device__ float g_qT[64 * NQ_MAX];     // k-major query features
__device__ float g_xn[NQ_MAX];          // ||q_h||^2
__device__ float g_w[3 * NQ_MAX];       // softplus weights per query

// packed f32x2 FMA: d = a*b + d (lanewise on 2 packed floats)
__device__ __forceinline__ void ffma2(ull& d, ull a, ull b) {
    asm("fma.rn.f32x2 %0, %1, %2, %0;" : "+l"(d) : "l"(a), "l"(b));
}
__device__ __forceinline__ float fold2(ull v) {
    return __uint_as_float((unsigned)v) + __uint_as_float((unsigned)(v >> 32));
}

// ---------------------------------------------------------------------------
// Kernel A: corpus projection. Block = 64 corpus rows, 256 threads.
// thread (kp = tid&31, rg = tid>>5) computes features kp AND kp+32 for rows
// rg*8 .. rg*8+7. Packed-k f32x2 mainloop; x-tile loads broadcast per warp
// and amortized over the 2 features.
// ---------------------------------------------------------------------------
#define XSTRIDE 34   // float2 units per row (32 kk + 2 pad); 272B lane stride -> conflict-free

__global__ __launch_bounds__(256, 2) void corpus_proj_kernel(
    const float* __restrict__ xc,
    const float* __restrict__ We, const float* __restrict__ be,
    const float* __restrict__ Wh, const float* __restrict__ bh,
    const float* __restrict__ Ws, const float* __restrict__ bs,
    const float* __restrict__ scale_h_p, int NC)
{
    // pool: xs2 (64*34 float2) + wt2 (64*34 float2); transpose buffer overlays
    __shared__ __align__(16) float pool[2 * 64 * XSTRIDE * 2];
    __shared__ float sm_yn[64];
    float2* xs2 = (float2*)pool;                    // [row][kk]
    float2* wt2 = (float2*)pool + 64 * XSTRIDE;     // [feat][kk]

    const int tid = threadIdx.x;
    const int kp  = tid & 31;          // feature A = kp (e), feature B = kp+32 (h/s)
    const int rg  = tid >> 5;          // 0..7, 8 rows each
    const int c0  = blockIdx.x * 64;
    const int fB  = kp + 32;

    const float biasA = be[kp];
    const float biasB = (kp < 16) ? bh[kp] : bs[kp - 16];

    ull accA[8], accB[8];
#pragma unroll
    for (int i = 0; i < 8; i++) { accA[i] = 0ull; accB[i] = 0ull; }

    const int j4 = tid & 15;           // float4 column within tile
    const int r0 = tid >> 4;           // base row / feature for loads

    for (int k0 = 0; k0 < D_IN; k0 += 64) {
        __syncthreads();
        // x tile: 64 rows x 64 k as float4 LDG, STS.128 into [row][kk] pairs
#pragma unroll
        for (int it = 0; it < 4; it++) {
            int r = r0 + it * 16;
            float4 v = *(const float4*)&xc[(size_t)(c0 + r) * D_IN + k0 + j4 * 4];
            *(float4*)&xs2[r * XSTRIDE + j4 * 2] = v;
        }
        // weight tile: wt2[kf][kk] pairs along input dim
#pragma unroll
        for (int it = 0; it < 4; it++) {
            int kf = r0 + it * 16;
            const float* wr = (kf < 32) ? (We + kf * D_IN)
                            : (kf < 48) ? (Wh + (kf - 32) * D_IN)
                                        : (Ws + (kf - 48) * D_IN);
            float4 v = *(const float4*)&wr[k0 + j4 * 4];
            *(float4*)&wt2[kf * XSTRIDE + j4 * 2] = v;
        }
        __syncthreads();

        const float2* xrow = xs2 + rg * 8 * XSTRIDE;   // uniform per warp -> broadcast
#pragma unroll 8
        for (int kk = 0; kk < 32; kk += 2) {
            ulonglong2 wA = *(const ulonglong2*)&wt2[kp * XSTRIDE + kk];
            ulonglong2 wB = *(const ulonglong2*)&wt2[fB * XSTRIDE + kk];
#pragma unroll
            for (int u = 0; u < 8; u++) {
                ulonglong2 xv = *(const ulonglong2*)&xrow[u * XSTRIDE + kk]; // broadcast
                ffma2(accA[u], xv.x, wA.x);
                ffma2(accA[u], xv.y, wA.y);
                ffma2(accB[u], xv.x, wB.x);
                ffma2(accB[u], xv.y, wB.y);
            }
        }
    }

    // fold packed halves, add bias (+ scale_h for hyperbolic branch)
    const float sh = scale_h_p[0];
    const bool isH = (kp < 16);        // feature B type
    float aA[8], aB[8];
#pragma unroll
    for (int i = 0; i < 8; i++) {
        aA[i] = fold2(accA[i]) + biasA;
        float v = fold2(accB[i]) + biasB;
        if (isH) v *= sh;
        aB[i] = v;
    }

    const unsigned FULL = 0xffffffffu;
    // feature A: e-norm over full warp
#pragma unroll
    for (int i = 0; i < 8; i++) {
        float s = aA[i] * aA[i];
        s += __shfl_xor_sync(FULL, s, 16);
        s += __shfl_xor_sync(FULL, s, 8);
        s += __shfl_xor_sync(FULL, s, 4);
        s += __shfl_xor_sync(FULL, s, 2);
        s += __shfl_xor_sync(FULL, s, 1);
        aA[i] *= rsqrtf(s);
    }
    // feature B: lanes 0..15 = h (expmap0), lanes 16..31 = s (normalize); 16-lane groups
#pragma unroll
    for (int i = 0; i < 8; i++) {
        float s = aB[i] * aB[i];
        s += __shfl_xor_sync(FULL, s, 8);
        s += __shfl_xor_sync(FULL, s, 4);
        s += __shfl_xor_sync(FULL, s, 2);
        s += __shfl_xor_sync(FULL, s, 1);
        if (isH) {
            float n  = fmaxf(sqrtf(s), 1e-15f);
            float tn = tanhf(n);
            aB[i] = aB[i] * (tn / n);
            if (kp == 0) sm_yn[rg * 8 + i] = tn * tn;
        } else {
            aB[i] *= rsqrtf(s);
        }
    }

    // transpose through smem (overlay pool) for coalesced k-major global writes
    __syncthreads();
    float* st = pool;   // needs 64*65 = 4160 floats; pool has 8704
#pragma unroll
    for (int i = 0; i < 8; i++) {
        st[kp * 65 + rg * 8 + i] = aA[i];
        st[fB * 65 + rg * 8 + i] = aB[i];
    }
    __syncthreads();
#pragma unroll
    for (int it = 0; it < 16; it++) {
        int idx = tid + it * 256;
        int kf = idx >> 6, r = idx & 63;
        g_cT[(size_t)kf * NC + c0 + r] = st[kf * 65 + r];
    }
    if (tid < 64) g_yn[c0 + tid] = sm_yn[tid];
}

// ---------------------------------------------------------------------------
// Kernel B: query projection + softplus-MLP weights. One block per query.
// ---------------------------------------------------------------------------
__global__ __launch_bounds__(128) void query_proj_kernel(
    const float* __restrict__ xq,
    const float* __restrict__ We, const float* __restrict__ be,
    const float* __restrict__ Wh, const float* __restrict__ bh,
    const float* __restrict__ Ws, const float* __restrict__ bs,
    const float* __restrict__ scale_h_p,
    const float* __restrict__ W1, const float* __restrict__ b1,
    const float* __restrict__ W2, const float* __restrict__ b2,
    int NQ)
{
    __shared__ float x[D_IN];
    __shared__ float raw[96];
    const int tid = threadIdx.x;
    const int qi  = blockIdx.x;

    for (int j = tid; j < D_IN; j += 128) x[j] = xq[(size_t)qi * D_IN + j];
    __syncthreads();

    if (tid < 96) {
        const float* Wr; float b;
        if (tid < 32)      { Wr = We + tid * D_IN;        b = be[tid]; }
        else if (tid < 48) { Wr = Wh + (tid - 32) * D_IN; b = bh[tid - 32]; }
        else if (tid < 64) { Wr = Ws + (tid - 48) * D_IN; b = bs[tid - 48]; }
        else               { Wr = W1 + (tid - 64) * D_IN; b = b1[tid - 64]; }
        float a0 = 0.f, a1 = 0.f, a2 = 0.f, a3 = 0.f;
#pragma unroll 4
        for (int j = 0; j < D_IN; j += 4) {
            const float4 wv = *(const float4*)&Wr[j];
            a0 = fmaf(x[j + 0], wv.x, a0);
            a1 = fmaf(x[j + 1], wv.y, a1);
            a2 = fmaf(x[j + 2], wv.z, a2);
            a3 = fmaf(x[j + 3], wv.w, a3);
        }
        float acc = (a0 + a1) + (a2 + a3) + b;
        if (tid >= 32 && tid < 48) acc *= scale_h_p[0];
        raw[tid] = acc;
    }
    __syncthreads();

    const unsigned FULL = 0xffffffffu;
    const int warp = tid >> 5, lane = tid & 31;
    if (warp == 0) {
        float v = raw[lane];
        float s = v * v;
        s += __shfl_xor_sync(FULL, s, 16);
        s += __shfl_xor_sync(FULL, s, 8);
        s += __shfl_xor_sync(FULL, s, 4);
        s += __shfl_xor_sync(FULL, s, 2);
        s += __shfl_xor_sync(FULL, s, 1);
        g_qT[(size_t)lane * NQ + qi] = v / sqrtf(s);
    } else if (warp == 1) {
        float v = (lane < 16) ? raw[32 + lane] : raw[48 + (lane - 16)];
        float s = v * v;
        s += __shfl_xor_sync(FULL, s, 8);
        s += __shfl_xor_sync(FULL, s, 4);
        s += __shfl_xor_sync(FULL, s, 2);
        s += __shfl_xor_sync(FULL, s, 1);
        if (lane < 16) {
            float n  = fmaxf(sqrtf(s), 1e-15f);
            float tn = tanhf(n);
            g_qT[(size_t)(32 + lane) * NQ + qi] = v * (tn / n);
            if (lane == 0) g_xn[qi] = tn * tn;
        } else {
            g_qT[(size_t)(48 + (lane - 16)) * NQ + qi] = v / sqrtf(s);
        }
    } else if (warp == 2) {
        float h = fmaxf(raw[64 + lane], 0.f);
#pragma unroll
        for (int j = 0; j < 3; j++) {
            float p = h * W2[j * 32 + lane];
            p += __shfl_xor_sync(FULL, p, 16);
            p += __shfl_xor_sync(FULL, p, 8);
            p += __shfl_xor_sync(FULL, p, 4);
            p += __shfl_xor_sync(FULL, p, 2);
            p += __shfl_xor_sync(FULL, p, 1);
            if (lane == 0) {
                p += b2[j];
                float sp = (p > 0.f) ? (p + log1pf(expf(-p))) : log1pf(expf(p));
                g_w[j * NQ + qi] = sp;
            }
        }
    }
}

// ---------------------------------------------------------------------------
// Kernel C: pairwise distances. 64q x 64c tile per block, 256 threads.
// Warp w = q rows 8w..8w+7 (q loads BROADCAST); lane l = c cols 2l,2l+1.
// Thread tile 8q x 2c; packed-k f32x2; per-segment accumulator fold.
// smem layout: [kk][r] of float2 = (feat[2kk][r], feat[2kk+1][r]).
// ---------------------------------------------------------------------------
__global__ __launch_bounds__(256, 2) void pairwise_kernel(
    float* __restrict__ out, int NQ, int NC)
{
    __shared__ __align__(16) float qs2[32 * 64 * 2];
    __shared__ __align__(16) float cs2[32 * 64 * 2];
    __shared__ float xns[64], yns[64], w0s[64], w1s[64], w2s[64];

    const int tid = threadIdx.x;
    const int q0 = blockIdx.y * 64;
    const int c0 = blockIdx.x * 64;

#pragma unroll
    for (int it = 0; it < 16; it++) {
        int idx = tid + it * 256;       // 0..4095
        int kf = idx >> 6, r = idx & 63;
        int saddr = ((kf >> 1) * 64 + r) * 2 + (kf & 1);
        qs2[saddr] = g_qT[(size_t)kf * NQ + q0 + r];
        cs2[saddr] = g_cT[(size_t)kf * NC + c0 + r];
    }
    if (tid < 64) {
        xns[tid] = g_xn[q0 + tid];
        yns[tid] = g_yn[c0 + tid];
        w0s[tid] = g_w[0 * NQ + q0 + tid];
        w1s[tid] = g_w[1 * NQ + q0 + tid];
        w2s[tid] = g_w[2 * NQ + q0 + tid];
    }
    __syncthreads();

    const int lane = tid & 31, w = tid >> 5;
    const ulonglong2* qp = (const ulonglong2*)qs2;   // 32 ulonglong2 per kk row
    const ulonglong2* cp = (const ulonglong2*)cs2;

    ull acc2[16];                    // [q-row 0..7][c 0..1]
    float aE[16], aH[16];

#define MMA_STEP(kk)                                                        \
    {                                                                       \
        ulonglong2 cv = cp[(kk) * 32 + lane];            /* lane-distinct */\
        ulonglong2 q0v = qp[(kk) * 32 + w * 4 + 0];      /* broadcast */    \
        ulonglong2 q1v = qp[(kk) * 32 + w * 4 + 1];                         \
        ulonglong2 q2v = qp[(kk) * 32 + w * 4 + 2];                         \
        ulonglong2 q3v = qp[(kk) * 32 + w * 4 + 3];                         \
        ffma2(acc2[ 0], q0v.x, cv.x); ffma2(acc2[ 1], q0v.x, cv.y);         \
        ffma2(acc2[ 2], q0v.y, cv.x); ffma2(acc2[ 3], q0v.y, cv.y);         \
        ffma2(acc2[ 4], q1v.x, cv.x); ffma2(acc2[ 5], q1v.x, cv.y);         \
        ffma2(acc2[ 6], q1v.y, cv.x); ffma2(acc2[ 7], q1v.y, cv.y);         \
        ffma2(acc2[ 8], q2v.x, cv.x); ffma2(acc2[ 9], q2v.x, cv.y);         \
        ffma2(acc2[10], q2v.y, cv.x); ffma2(acc2[11], q2v.y, cv.y);         \
        ffma2(acc2[12], q3v.x, cv.x); ffma2(acc2[13], q3v.x, cv.y);         \
        ffma2(acc2[14], q3v.y, cv.x); ffma2(acc2[15], q3v.y, cv.y);         \
    }

    // E segment: kk 0..15 (k 0..31)
#pragma unroll
    for (int i = 0; i < 16; i++) acc2[i] = 0ull;
#pragma unroll
    for (int kk = 0; kk < 16; kk++) MMA_STEP(kk);
#pragma unroll
    for (int i = 0; i < 16; i++) { aE[i] = fold2(acc2[i]); acc2[i] = 0ull; }

    // H segment: kk 16..23 (k 32..47)
#pragma unroll
    for (int kk = 16; kk < 24; kk++) MMA_STEP(kk);
#pragma unroll
    for (int i = 0; i < 16; i++) { aH[i] = fold2(acc2[i]); acc2[i] = 0ull; }

    // S segment: kk 24..31 (k 48..63)
#pragma unroll
    for (int kk = 24; kk < 32; kk++) MMA_STEP(kk);

#pragma unroll
    for (int i = 0; i < 8; i++) {
        const int ql   = w * 8 + i;
        const float xn   = xns[ql];
        const float beta = 1.f - xn;
        const float w0 = w0s[ql], w1 = w1s[ql], w2 = w2s[ql];
        float r2[2];
#pragma unroll
        for (int j = 0; j < 2; j++) {
            const int cl = lane * 2 + j;
            // euclidean on unit sphere
            float de = 2.f - 2.f * aE[i * 2 + j];
            // spherical
            float dsd = fminf(fmaxf(fold2(acc2[i * 2 + j]), -1.f + EPSF), 1.f - EPSF);
            float ac  = acosf(dsd);
            float dss = ac * ac;
            // hyperbolic (Poincare, c=1): dh = 2*atanh(t) = log((den+sn)/(den-sn))
            float dot = aH[i * 2 + j];
            float yn  = yns[cl];
            float alpha  = 1.f - 2.f * dot + yn;
            float num_sq = alpha * alpha * xn - 2.f * alpha * beta * dot + beta * beta * yn;
            float den    = fmaxf(1.f - 2.f * dot + xn * yn, 1e-15f);
            float sn = sqrtf(fmaxf(num_sq, 0.f));
            sn = fminf(sn, den * (1.f - EPSF));       // t <= 1 - EPS
            float dh  = __logf(__fdividef(den + sn, den - sn));
            float dhs = dh * dh;
            r2[j] = -(w0 * de + w1 * dhs + w2 * dss);
        }
        *(float2*)&out[(size_t)(q0 + ql) * NC + c0 + lane * 2] =
            make_float2(r2[0], r2[1]);
    }
#undef MMA_STEP
}

// ---------------------------------------------------------------------------
extern "C" void kernel_launch(void* const* d_in, const int* in_sizes, int n_in,
                              void* d_out, int out_size)
{
    const float* xq      = (const float*)d_in[0];
    const float* xc      = (const float*)d_in[1];
    const float* We      = (const float*)d_in[2];
    const float* be      = (const float*)d_in[3];
    const float* Wh      = (const float*)d_in[4];
    const float* bh      = (const float*)d_in[5];
    const float* Ws      = (const float*)d_in[6];
    const float* bs      = (const float*)d_in[7];
    const float* scale_h = (const float*)d_in[8];
    const float* W1      = (const float*)d_in[9];
    const float* b1      = (const float*)d_in[10];
    const float* W2      = (const float*)d_in[11];
    const float* b2      = (const float*)d_in[12];

    const int NQ = in_sizes[0] / D_IN;   // 512
    const int NC = in_sizes[1] / D_IN;   // 65536

    corpus_proj_kernel<<<NC / 64, 256>>>(xc, We, be, Wh, bh, Ws, bs, scale_h, NC);
    query_proj_kernel<<<NQ, 128>>>(xq, We, be, Wh, bh, Ws, bs, scale_h, W1, b1, W2, b2, NQ);
    pairwise_kernel<<<dim3(NC / 64, NQ / 64), 256>>>((float*)d_out, NQ, NC);
}